// round 1
// baseline (speedup 1.0000x reference)
#include <cuda_runtime.h>
#include <math.h>

#define H 256
#define BM 64
#define KC 64
#define NSEG 512

// scratch (no allocations allowed)
__device__ int g_counts[NSEG];
__device__ int g_is64;

// ---------------------------------------------------------------------------
// Kernel 1: zero output + counts, detect batch dtype (int64 vs int32).
// jax.random.randint(dtype=int64) silently demotes to int32 without x64, so we
// probe: viewing the buffer as int32, odd words near the end are all 0 iff the
// data is little-endian int64 (high halves of small segment ids). Only touches
// words < N, which is in-bounds for both dtypes.
// ---------------------------------------------------------------------------
__global__ void zero_kernel(float* out, int out_size, const void* batch, int N) {
    int i = blockIdx.x * blockDim.x + threadIdx.x;
    if (i < out_size) out[i] = 0.0f;
    if (i < NSEG) g_counts[i] = 0;
    if (i == 0) {
        const int* bw = (const int*)batch;
        int o = ((N - 1) & 1) ? (N - 1) : (N - 2);   // largest odd index < N
        int orv = 0;
        if (o >= 4) orv = bw[o] | bw[o - 2] | bw[o - 4];
        else if (o >= 0) orv = bw[o];
        g_is64 = (orv == 0) ? 1 : 0;
    }
}

// ---------------------------------------------------------------------------
// Kernel 2: fused  relu(xW1^T+b1) -> sigmoid(hW2^T+b2) gate -> segment reduce.
// 64-row tile per block, 256 threads, thread tile 8 rows x 8 cols.
// rows:  r = rr*8 + tr   (tr = tid/32, warp-uniform -> broadcast smem reads)
// cols:  c = cc*32 + tc  (tc = tid%32, stride-32 -> conflict-free W reads)
// ---------------------------------------------------------------------------
extern "C" __global__ void __launch_bounds__(256, 1)
fused_kernel(const float* __restrict__ x, const void* __restrict__ batch,
             const float* __restrict__ W1, const float* __restrict__ b1,
             const float* __restrict__ W2, const float* __restrict__ b2,
             float* __restrict__ out, int N)
{
    extern __shared__ float smem[];
    float* xs = smem;                     // [BM][H]   x tile, then h tile, then g tile
    float* ws = smem + BM * H;            // [KC][H+1] W chunk (k-major, padded)
    int*   bseg = (int*)(ws + KC * (H + 1)); // [BM] segment ids

    const int tid = threadIdx.x;
    const int tr  = tid >> 5;             // 0..7
    const int tc  = tid & 31;             // 0..31
    const int row0 = blockIdx.x * BM;

    // ---- load x tile (float4, coalesced) + segment ids ----
    {
        const float4* xg = (const float4*)x;
        #pragma unroll
        for (int it = 0; it < 16; ++it) {
            int f = tid + it * 256;       // float4 index within tile
            int r = f >> 6, k4 = f & 63;
            float4 v = make_float4(0.f, 0.f, 0.f, 0.f);
            if (row0 + r < N) v = xg[(size_t)(row0 + r) * (H / 4) + k4];
            ((float4*)(xs + r * H))[k4] = v;
        }
        if (tid < BM) {
            int r = row0 + tid;
            int s = -1;
            if (r < N) {
                if (g_is64) s = (int)((const long long*)batch)[r];
                else        s = ((const int*)batch)[r];
            }
            bseg[tid] = s;
        }
    }

    float h[8][8];
    float acc[8][8];
    #pragma unroll
    for (int i = 0; i < 8; ++i)
        #pragma unroll
        for (int j = 0; j < 8; ++j) acc[i][j] = 0.f;

    // =================== GEMM1: acc = x @ W1^T ===================
    for (int k0 = 0; k0 < H; k0 += KC) {
        __syncthreads();
        // ws[kk][j] = W1[j][k0+kk]  (float4 along k, coalesced global reads)
        const float4* wg = (const float4*)W1;
        #pragma unroll
        for (int it = 0; it < 16; ++it) {
            int f4 = tid + it * 256;      // 4096 float4s per chunk
            int kk4 = f4 & 15, j = f4 >> 4;
            float4 v = wg[(size_t)j * (H / 4) + (k0 >> 2) + kk4];
            ws[(kk4 * 4 + 0) * (H + 1) + j] = v.x;
            ws[(kk4 * 4 + 1) * (H + 1) + j] = v.y;
            ws[(kk4 * 4 + 2) * (H + 1) + j] = v.z;
            ws[(kk4 * 4 + 3) * (H + 1) + j] = v.w;
        }
        __syncthreads();
        #pragma unroll 4
        for (int kk = 0; kk < KC; ++kk) {
            float a[8], b[8];
            #pragma unroll
            for (int rr = 0; rr < 8; ++rr) a[rr] = xs[(rr * 8 + tr) * H + k0 + kk];
            #pragma unroll
            for (int cc = 0; cc < 8; ++cc) b[cc] = ws[kk * (H + 1) + tc + 32 * cc];
            #pragma unroll
            for (int rr = 0; rr < 8; ++rr)
                #pragma unroll
                for (int cc = 0; cc < 8; ++cc)
                    acc[rr][cc] += a[rr] * b[cc];
        }
    }

    // bias + relu -> h (registers), then publish h tile into xs
    #pragma unroll
    for (int cc = 0; cc < 8; ++cc) {
        float bb = b1[tc + 32 * cc];
        #pragma unroll
        for (int rr = 0; rr < 8; ++rr) {
            float v = acc[rr][cc] + bb;
            h[rr][cc] = v > 0.f ? v : 0.f;
        }
    }
    __syncthreads();   // everyone done reading x tile
    #pragma unroll
    for (int rr = 0; rr < 8; ++rr)
        #pragma unroll
        for (int cc = 0; cc < 8; ++cc)
            xs[(rr * 8 + tr) * H + tc + 32 * cc] = h[rr][cc];

    #pragma unroll
    for (int i = 0; i < 8; ++i)
        #pragma unroll
        for (int j = 0; j < 8; ++j) acc[i][j] = 0.f;

    // =================== GEMM2: acc = h @ W2^T ===================
    for (int k0 = 0; k0 < H; k0 += KC) {
        __syncthreads();                  // also covers h-tile visibility on first iter
        const float4* wg = (const float4*)W2;
        #pragma unroll
        for (int it = 0; it < 16; ++it) {
            int f4 = tid + it * 256;
            int kk4 = f4 & 15, j = f4 >> 4;
            float4 v = wg[(size_t)j * (H / 4) + (k0 >> 2) + kk4];
            ws[(kk4 * 4 + 0) * (H + 1) + j] = v.x;
            ws[(kk4 * 4 + 1) * (H + 1) + j] = v.y;
            ws[(kk4 * 4 + 2) * (H + 1) + j] = v.z;
            ws[(kk4 * 4 + 3) * (H + 1) + j] = v.w;
        }
        __syncthreads();
        #pragma unroll 4
        for (int kk = 0; kk < KC; ++kk) {
            float a[8], b[8];
            #pragma unroll
            for (int rr = 0; rr < 8; ++rr) a[rr] = xs[(rr * 8 + tr) * H + k0 + kk];
            #pragma unroll
            for (int cc = 0; cc < 8; ++cc) b[cc] = ws[kk * (H + 1) + tc + 32 * cc];
            #pragma unroll
            for (int rr = 0; rr < 8; ++rr)
                #pragma unroll
                for (int cc = 0; cc < 8; ++cc)
                    acc[rr][cc] += a[rr] * b[cc];
        }
    }

    // g = h * sigmoid(acc + b2), overwrite xs with g
    __syncthreads();   // everyone done reading h tile
    #pragma unroll
    for (int cc = 0; cc < 8; ++cc) {
        float bb = b2[tc + 32 * cc];
        #pragma unroll
        for (int rr = 0; rr < 8; ++rr) {
            float s = 1.f / (1.f + __expf(-(acc[rr][cc] + bb)));
            xs[(rr * 8 + tr) * H + tc + 32 * cc] = h[rr][cc] * s;
        }
    }
    __syncthreads();

    // ---- segment reduction: batch is sorted, so rows form runs. One thread
    // per column scans 64 rows, flushing one atomicAdd/atomicMax per run. ----
    {
        const int c = tid;                 // 256 threads = 256 columns
        int cur = bseg[0];
        float rsum = 0.f, rmax = 0.f;
        #pragma unroll 1
        for (int r = 0; r < BM; ++r) {
            int s = bseg[r];
            float g = xs[r * H + c];
            if (s != cur) {
                if (cur >= 0) {
                    atomicAdd(&out[(size_t)cur * 2 * H + H + c], rsum);
                    atomicMax((unsigned int*)&out[(size_t)cur * 2 * H + c],
                              __float_as_uint(rmax));   // g >= 0 always
                }
                cur = s; rsum = 0.f; rmax = 0.f;
            }
            if (s >= 0) { rsum += g; rmax = fmaxf(rmax, g); }
        }
        if (cur >= 0) {
            atomicAdd(&out[(size_t)cur * 2 * H + H + c], rsum);
            atomicMax((unsigned int*)&out[(size_t)cur * 2 * H + c],
                      __float_as_uint(rmax));
        }
        if (tid == 0) {                    // counts: once per run per tile
            int cur2 = bseg[0]; int cnt = 0;
            for (int r = 0; r < BM; ++r) {
                int s = bseg[r];
                if (s != cur2) {
                    if (cur2 >= 0) atomicAdd(&g_counts[cur2], cnt);
                    cur2 = s; cnt = 0;
                }
                if (s >= 0) cnt++;
            }
            if (cur2 >= 0) atomicAdd(&g_counts[cur2], cnt);
        }
    }
}

// ---------------------------------------------------------------------------
// Kernel 3: mean = sum / count (empty segments stay 0: sum is 0, divide by 1)
// ---------------------------------------------------------------------------
__global__ void finalize_kernel(float* out) {
    int i = blockIdx.x * blockDim.x + threadIdx.x;  // NSEG * H
    if (i < NSEG * H) {
        int seg = i >> 8;
        int c   = i & (H - 1);
        int cnt = g_counts[seg];
        float denom = cnt > 0 ? (float)cnt : 1.f;
        out[(size_t)seg * 2 * H + H + c] *= (1.f / denom);
    }
}

extern "C" void kernel_launch(void* const* d_in, const int* in_sizes, int n_in,
                              void* d_out, int out_size) {
    const float* x     = (const float*)d_in[0];
    const void*  batch = d_in[1];
    const float* W1    = (const float*)d_in[2];
    const float* b1    = (const float*)d_in[3];
    const float* W2    = (const float*)d_in[4];
    const float* b2    = (const float*)d_in[5];
    float* out = (float*)d_out;

    int N = in_sizes[0] / H;

    const int smem_bytes = (BM * H + KC * (H + 1)) * 4 + BM * 4;  // 131584
    cudaFuncSetAttribute(fused_kernel,
                         cudaFuncAttributeMaxDynamicSharedMemorySize, smem_bytes);

    zero_kernel<<<(out_size + 255) / 256, 256>>>(out, out_size, batch, N);

    int nblk = (N + BM - 1) / BM;
    fused_kernel<<<nblk, 256, smem_bytes>>>(x, batch, W1, b1, W2, b2, out, N);

    finalize_kernel<<<(NSEG * H + 255) / 256, 256>>>(out);
}

// round 3
// speedup vs baseline: 1.0426x; 1.0426x over previous
#include <cuda_runtime.h>
#include <cstdint>
#include <math.h>

#define H 256
#define BM 64
#define KC 64
#define NSEG 512

// scratch (no allocations allowed)
__device__ int   g_counts[NSEG];
__device__ int   g_is64;
__device__ float g_Wt[2][H * H];   // W1^T, W2^T  (k-major)

typedef unsigned long long u64;
typedef unsigned int       u32;

__device__ __forceinline__ u64 pk2(float v) {
    u64 r; asm("mov.b64 %0,{%1,%1};" : "=l"(r) : "f"(v)); return r;
}
__device__ __forceinline__ u64 fma2(u64 a, u64 b, u64 c) {
    u64 d; asm("fma.rn.f32x2 %0,%1,%2,%3;" : "=l"(d) : "l"(a), "l"(b), "l"(c)); return d;
}
__device__ __forceinline__ float2 upk(u64 v) {
    float2 f; asm("mov.b64 {%0,%1},%2;" : "=f"(f.x), "=f"(f.y) : "l"(v)); return f;
}
__device__ __forceinline__ void cpasync16(u32 dst, const void* src) {
    asm volatile("cp.async.cg.shared.global [%0],[%1],16;" :: "r"(dst), "l"(src));
}
__device__ __forceinline__ void cpcommit() {
    asm volatile("cp.async.commit_group;");
}

// ---------------------------------------------------------------------------
// Kernel 1: zero output + counts, detect batch dtype (int64 vs int32).
// ---------------------------------------------------------------------------
__global__ void zero_kernel(float* out, int out_size, const void* batch, int N) {
    int i = blockIdx.x * blockDim.x + threadIdx.x;
    if (i < out_size) out[i] = 0.0f;
    if (i < NSEG) g_counts[i] = 0;
    if (i == 0) {
        const int* bw = (const int*)batch;
        int o = ((N - 1) & 1) ? (N - 1) : (N - 2);   // largest odd index < N
        int orv = 0;
        if (o >= 4) orv = bw[o] | bw[o - 2] | bw[o - 4];
        else if (o >= 0) orv = bw[o];
        g_is64 = (orv == 0) ? 1 : 0;
    }
}

// ---------------------------------------------------------------------------
// Kernel 2: transpose W1, W2 into g_Wt (k-major) so the fused kernel's smem
// staging is a plain contiguous copy (conflict-free, cp.async friendly).
// grid (64, 2), 256 threads: 32x32 tiles.
// ---------------------------------------------------------------------------
__global__ void transpose_kernel(const float* __restrict__ W1,
                                 const float* __restrict__ W2) {
    __shared__ float t[32][33];
    const float* W = blockIdx.y ? W2 : W1;
    float* Wt = g_Wt[blockIdx.y];
    int bx = (blockIdx.x & 7) * 32;    // k tile
    int by = (blockIdx.x >> 3) * 32;   // j tile
    int lx = threadIdx.x & 31, r0 = threadIdx.x >> 5;
    #pragma unroll
    for (int s = 0; s < 4; ++s) {
        int r = r0 + s * 8;
        t[r][lx] = W[(size_t)(by + r) * H + bx + lx];
    }
    __syncthreads();
    #pragma unroll
    for (int s = 0; s < 4; ++s) {
        int r = r0 + s * 8;
        Wt[(size_t)(bx + r) * H + by + lx] = t[lx][r];
    }
}

// ---------------------------------------------------------------------------
// Kernel 3: fused  relu(xW1^T+b1) -> sigmoid(hW2^T+b2) gate -> segment reduce.
// 64-row tile per block, 256 threads.
//   rows: r = rr*8 + tr     (tr = tid/32, warp-uniform -> smem broadcast)
//   cols: c = cc*128 + tc*4 + q   (cc=0..1, q=0..3) -> LDS.128 B-fragments
// Accumulators are f32x2 pairs (adjacent columns) updated with fma.rn.f32x2.
// W chunks double-buffered via cp.async (8 chunks: 4 of W1t then 4 of W2t).
// ---------------------------------------------------------------------------
extern "C" __global__ void __launch_bounds__(256, 1)
fused_kernel(const float* __restrict__ x, const void* __restrict__ batch,
             const float* __restrict__ b1, const float* __restrict__ b2,
             float* __restrict__ out, int N)
{
    extern __shared__ float smem[];
    float* xs  = smem;                    // [BM][H]  x tile -> h tile -> g tile
    float* wsb[2];
    wsb[0] = smem + BM * H;               // [KC][H]  W chunk buffer 0
    wsb[1] = wsb[0] + KC * H;             // [KC][H]  W chunk buffer 1
    int*   bseg = (int*)(wsb[1] + KC * H);

    const int tid = threadIdx.x;
    const int tr  = tid >> 5;             // 0..7
    const int tc  = tid & 31;             // 0..31
    const int row0 = blockIdx.x * BM;

    // ---- issue chunk 0 prefetch immediately ----
    u32 wdst[2];
    wdst[0] = (u32)__cvta_generic_to_shared(wsb[0]) + tid * 16;
    wdst[1] = (u32)__cvta_generic_to_shared(wsb[1]) + tid * 16;
    {
        const float* gp = g_Wt[0] + tid * 4;
        #pragma unroll
        for (int it = 0; it < 16; ++it)
            cpasync16(wdst[0] + it * 4096, gp + it * 1024);
        cpcommit();
    }

    // ---- load x tile (float4, coalesced) + segment ids ----
    {
        const float4* xg = (const float4*)x;
        #pragma unroll
        for (int it = 0; it < 16; ++it) {
            int f = tid + it * 256;       // float4 index within tile
            int r = f >> 6, k4 = f & 63;
            float4 v = make_float4(0.f, 0.f, 0.f, 0.f);
            if (row0 + r < N) v = xg[(size_t)(row0 + r) * (H / 4) + k4];
            ((float4*)(xs + r * H))[k4] = v;
        }
        if (tid < BM) {
            int r = row0 + tid;
            int s = -1;
            if (r < N) {
                if (g_is64) s = (int)((const long long*)batch)[r];
                else        s = ((const int*)batch)[r];
            }
            bseg[tid] = s;
        }
    }

    u64 acc[8][4];
    #pragma unroll
    for (int i = 0; i < 8; ++i)
        #pragma unroll
        for (int j = 0; j < 4; ++j) acc[i][j] = 0ull;

    // ---- 8 chunks: i=0..3 GEMM1 (W1t), i=4..7 GEMM2 (W2t) ----
    #pragma unroll 1
    for (int i = 0; i < 8; ++i) {
        // prefetch next chunk into the other buffer
        if (i < 7) {
            int n = i + 1;
            const float* gp = g_Wt[n >> 2] + (size_t)(n & 3) * KC * H + tid * 4;
            u32 d = wdst[n & 1];
            #pragma unroll
            for (int it = 0; it < 16; ++it)
                cpasync16(d + it * 4096, gp + it * 1024);
            cpcommit();
            asm volatile("cp.async.wait_group 1;");
        } else {
            asm volatile("cp.async.wait_group 0;");
        }
        __syncthreads();   // chunk i buffer visible to all

        // between GEMM1 and GEMM2: bias+relu, publish h into xs
        if (i == 4) {
            float2 bb[4];
            bb[0] = *(const float2*)&b1[tc * 4];
            bb[1] = *(const float2*)&b1[tc * 4 + 2];
            bb[2] = *(const float2*)&b1[128 + tc * 4];
            bb[3] = *(const float2*)&b1[128 + tc * 4 + 2];
            #pragma unroll
            for (int rr = 0; rr < 8; ++rr) {
                int row = rr * 8 + tr;
                float4 h0, h1;
                float2 v0 = upk(acc[rr][0]), v1 = upk(acc[rr][1]);
                float2 v2 = upk(acc[rr][2]), v3 = upk(acc[rr][3]);
                h0.x = fmaxf(v0.x + bb[0].x, 0.f);
                h0.y = fmaxf(v0.y + bb[0].y, 0.f);
                h0.z = fmaxf(v1.x + bb[1].x, 0.f);
                h0.w = fmaxf(v1.y + bb[1].y, 0.f);
                h1.x = fmaxf(v2.x + bb[2].x, 0.f);
                h1.y = fmaxf(v2.y + bb[2].y, 0.f);
                h1.z = fmaxf(v3.x + bb[3].x, 0.f);
                h1.w = fmaxf(v3.y + bb[3].y, 0.f);
                *(float4*)&xs[row * H + tc * 4]       = h0;
                *(float4*)&xs[row * H + 128 + tc * 4] = h1;
            }
            __syncthreads();   // h tile visible before GEMM2 reads it
            #pragma unroll
            for (int r2 = 0; r2 < 8; ++r2)
                #pragma unroll
                for (int j2 = 0; j2 < 4; ++j2) acc[r2][j2] = 0ull;
        }

        // ---- compute chunk i ----
        const float* ws = wsb[i & 1];
        const int k0 = (i & 3) * KC;
        #pragma unroll 2
        for (int kk = 0; kk < KC; ++kk) {
            const float* brow = ws + kk * H + tc * 4;
            ulonglong2 bq0 = *(const ulonglong2*)brow;          // cols tc*4..+3
            ulonglong2 bq1 = *(const ulonglong2*)(brow + 128);  // cols 128+tc*4..+3
            #pragma unroll
            for (int rr = 0; rr < 8; ++rr) {
                u64 a2 = pk2(xs[(rr * 8 + tr) * H + k0 + kk]);
                acc[rr][0] = fma2(a2, bq0.x, acc[rr][0]);
                acc[rr][1] = fma2(a2, bq0.y, acc[rr][1]);
                acc[rr][2] = fma2(a2, bq1.x, acc[rr][2]);
                acc[rr][3] = fma2(a2, bq1.y, acc[rr][3]);
            }
        }
        __syncthreads();   // all reads of this buffer done before it is refilled
    }

    // ---- epilogue: g = h * sigmoid(acc + b2) (h read back from xs) ----
    {
        float2 cb[4];
        cb[0] = *(const float2*)&b2[tc * 4];
        cb[1] = *(const float2*)&b2[tc * 4 + 2];
        cb[2] = *(const float2*)&b2[128 + tc * 4];
        cb[3] = *(const float2*)&b2[128 + tc * 4 + 2];
        #pragma unroll
        for (int rr = 0; rr < 8; ++rr) {
            int row = rr * 8 + tr;
            float4 h0 = *(float4*)&xs[row * H + tc * 4];
            float4 h1 = *(float4*)&xs[row * H + 128 + tc * 4];
            float2 v0 = upk(acc[rr][0]), v1 = upk(acc[rr][1]);
            float2 v2 = upk(acc[rr][2]), v3 = upk(acc[rr][3]);
            float4 g0, g1;
            g0.x = h0.x / (1.f + __expf(-(v0.x + cb[0].x)));
            g0.y = h0.y / (1.f + __expf(-(v0.y + cb[0].y)));
            g0.z = h0.z / (1.f + __expf(-(v1.x + cb[1].x)));
            g0.w = h0.w / (1.f + __expf(-(v1.y + cb[1].y)));
            g1.x = h1.x / (1.f + __expf(-(v2.x + cb[2].x)));
            g1.y = h1.y / (1.f + __expf(-(v2.y + cb[2].y)));
            g1.z = h1.z / (1.f + __expf(-(v3.x + cb[3].x)));
            g1.w = h1.w / (1.f + __expf(-(v3.y + cb[3].y)));
            *(float4*)&xs[row * H + tc * 4]       = g0;
            *(float4*)&xs[row * H + 128 + tc * 4] = g1;
        }
    }
    __syncthreads();

    // ---- segment reduction: batch sorted -> runs; one thread per column ----
    {
        const int c = tid;                 // 256 threads = 256 columns
        int cur = bseg[0];
        float rsum = 0.f, rmax = 0.f;
        #pragma unroll 1
        for (int r = 0; r < BM; ++r) {
            int s = bseg[r];
            float g = xs[r * H + c];
            if (s != cur) {
                if (cur >= 0) {
                    atomicAdd(&out[(size_t)cur * 2 * H + H + c], rsum);
                    atomicMax((unsigned int*)&out[(size_t)cur * 2 * H + c],
                              __float_as_uint(rmax));   // g >= 0 always
                }
                cur = s; rsum = 0.f; rmax = 0.f;
            }
            if (s >= 0) { rsum += g; rmax = fmaxf(rmax, g); }
        }
        if (cur >= 0) {
            atomicAdd(&out[(size_t)cur * 2 * H + H + c], rsum);
            atomicMax((unsigned int*)&out[(size_t)cur * 2 * H + c],
                      __float_as_uint(rmax));
        }
        if (tid == 0) {                    // counts: once per run per tile
            int cur2 = bseg[0]; int cnt = 0;
            for (int r = 0; r < BM; ++r) {
                int s = bseg[r];
                if (s != cur2) {
                    if (cur2 >= 0) atomicAdd(&g_counts[cur2], cnt);
                    cur2 = s; cnt = 0;
                }
                if (s >= 0) cnt++;
            }
            if (cur2 >= 0) atomicAdd(&g_counts[cur2], cnt);
        }
    }
}

// ---------------------------------------------------------------------------
// Kernel 4: mean = sum / count (empty segments stay 0)
// ---------------------------------------------------------------------------
__global__ void finalize_kernel(float* out) {
    int i = blockIdx.x * blockDim.x + threadIdx.x;  // NSEG * H
    if (i < NSEG * H) {
        int seg = i >> 8;
        int c   = i & (H - 1);
        int cnt = g_counts[seg];
        float denom = cnt > 0 ? (float)cnt : 1.f;
        out[(size_t)seg * 2 * H + H + c] *= (1.f / denom);
    }
}

extern "C" void kernel_launch(void* const* d_in, const int* in_sizes, int n_in,
                              void* d_out, int out_size) {
    const float* x     = (const float*)d_in[0];
    const void*  batch = d_in[1];
    const float* W1    = (const float*)d_in[2];
    const float* b1    = (const float*)d_in[3];
    const float* W2    = (const float*)d_in[4];
    const float* b2    = (const float*)d_in[5];
    float* out = (float*)d_out;

    int N = in_sizes[0] / H;

    const int smem_bytes = (BM * H + 2 * KC * H) * 4 + BM * 4;  // 196864
    cudaFuncSetAttribute(fused_kernel,
                         cudaFuncAttributeMaxDynamicSharedMemorySize, smem_bytes);

    zero_kernel<<<(out_size + 255) / 256, 256>>>(out, out_size, batch, N);
    transpose_kernel<<<dim3(64, 2), 256>>>(W1, W2);

    int nblk = (N + BM - 1) / BM;
    fused_kernel<<<nblk, 256, smem_bytes>>>(x, batch, b1, b2, out, N);

    finalize_kernel<<<(NSEG * H + 255) / 256, 256>>>(out);
}

// round 5
// speedup vs baseline: 1.3976x; 1.3405x over previous
#include <cuda_runtime.h>
#include <cuda_bf16.h>
#include <cstdint>
#include <math.h>

#define H 256
#define BM 64
#define NSEG 512
#define AS 528           // A row stride in bytes (264 bf16, padded)

typedef unsigned long long u64;
typedef unsigned int       u32;

// -------- device scratch (no allocations allowed) --------
__device__ int g_counts[NSEG];
__device__ int g_is64;
// W packed in per-lane b-fragment layout:
// [gemm(2)][mat hi/lo(2)][kchunk(4)] blocks of 8192 u32 = [ks(4)][nt(32)][lane(32)][reg(2)]
__device__ __align__(16) u32 g_Wb[131072];

// -------- SMEM layout (bytes) --------
#define OFF_AHI   0                    // [64][264] bf16 = 33792
#define OFF_ALO   33792                // 33792
#define OFF_B     67584                // 2 bufs x 65536 (each: [mat(2)][ks(4)][nt(32)][lane(32)][2]u32)
#define OFF_BSEG  198656               // 64 ints
#define OFF_BIAS  198912               // b1[256], b2[256] fp32
#define SMEM_TOTAL 200960
// gtile (final): fp32 [64][257] at OFF_B (B buffers dead by then)

// -------- PTX helpers (all legal on plain sm_103 target) --------
__device__ __forceinline__ void ldm4(u32* r, u32 addr) {
    asm volatile("ldmatrix.sync.aligned.m8n8.x4.shared.b16 {%0,%1,%2,%3},[%4];"
        : "=r"(r[0]), "=r"(r[1]), "=r"(r[2]), "=r"(r[3]) : "r"(addr));
}
__device__ __forceinline__ void lds64(u32* r, u32 addr) {
    asm volatile("ld.shared.v2.u32 {%0,%1},[%2];" : "=r"(r[0]), "=r"(r[1]) : "r"(addr));
}
__device__ __forceinline__ void mma16816(float* d, const u32* a, const u32* b) {
    asm volatile(
        "mma.sync.aligned.m16n8k16.row.col.f32.bf16.bf16.f32 "
        "{%0,%1,%2,%3},{%4,%5,%6,%7},{%8,%9},{%0,%1,%2,%3};"
        : "+f"(d[0]), "+f"(d[1]), "+f"(d[2]), "+f"(d[3])
        : "r"(a[0]), "r"(a[1]), "r"(a[2]), "r"(a[3]), "r"(b[0]), "r"(b[1]));
}
__device__ __forceinline__ void cpasync16(u32 dst, const void* src) {
    asm volatile("cp.async.cg.shared.global [%0],[%1],16;" :: "r"(dst), "l"(src));
}
#define CPCOMMIT() asm volatile("cp.async.commit_group;")

// ---------------------------------------------------------------------------
// Kernel 1: zero output + counts, detect batch dtype (int64 vs int32).
// ---------------------------------------------------------------------------
__global__ void zero_kernel(float* out, int out_size, const void* batch, int N) {
    int i = blockIdx.x * blockDim.x + threadIdx.x;
    if (i < out_size) out[i] = 0.0f;
    if (i < NSEG) g_counts[i] = 0;
    if (i == 0) {
        const int* bw = (const int*)batch;
        int o = ((N - 1) & 1) ? (N - 1) : (N - 2);
        int orv = 0;
        if (o >= 4) orv = bw[o] | bw[o - 2] | bw[o - 4];
        else if (o >= 0) orv = bw[o];
        g_is64 = (orv == 0) ? 1 : 0;
    }
}

// ---------------------------------------------------------------------------
// Kernel 2: split W1/W2 fp32 -> bf16 hi/lo, packed in mma b-fragment layout.
// One thread per (gemm, n, k): 512 blocks x 256 threads.
// b-frag mapping (m16n8k16 row.col): lane = (n&7)*4 + ((k&7)>>1),
//   reg = (k&15)>>3, half = k&1, tile: ks=(k>>4)&3, chunk=k>>6, nt=n>>3.
// ---------------------------------------------------------------------------
__global__ void wprep_kernel(const float* __restrict__ W1,
                             const float* __restrict__ W2) {
    int id = blockIdx.x * 256 + threadIdx.x;     // 131072 total
    int gemm = id >> 16, rem = id & 65535;
    int n = rem >> 8, k = rem & 255;
    float w = (gemm ? W2 : W1)[n * H + k];
    __nv_bfloat16 hi = __float2bfloat16(w);
    __nv_bfloat16 lo = __float2bfloat16(w - __bfloat162float(hi));
    int chunk = k >> 6, ks = (k >> 4) & 3, kk = k & 15;
    int nt = n >> 3, nn = n & 7;
    int lane = nn * 4 + ((kk & 7) >> 1);
    int reg  = kk >> 3;
    int half = kk & 1;
    u32 base = (u32)(((gemm * 2 + 0) * 4 + chunk) * 8192
                     + ((ks * 32 + nt) * 32 + lane) * 2 + reg);
    __nv_bfloat16* wb = (__nv_bfloat16*)g_Wb;
    wb[(size_t)base * 2 + half] = hi;                       // mat 0 (hi)
    wb[((size_t)base + 32768) * 2 + half] = lo;             // mat 1 (lo), +4*8192 u32
}

// ---------------------------------------------------------------------------
// Kernel 3: fused  relu(xW1^T+b1) -> sigmoid(hW2^T+b2) gate -> segment reduce
// via classic bf16 HMMA with 3-term hi/lo error compensation.
// ---------------------------------------------------------------------------
extern "C" __global__ void __launch_bounds__(256, 1)
fused_kernel(const float* __restrict__ x, const void* __restrict__ batch,
             const float* __restrict__ b1, const float* __restrict__ b2,
             float* __restrict__ out, int N)
{
    extern __shared__ char smem[];
    const u32 sb = (u32)__cvta_generic_to_shared(smem);
    const int tid  = threadIdx.x;
    const int w    = tid >> 5;          // warp 0..7: output cols w*32..w*32+31
    const int lane = tid & 31;
    const int row0 = blockIdx.x * BM;
    float* sb1 = (float*)(smem + OFF_BIAS);
    float* sb2 = sb1 + H;
    int* bseg = (int*)(smem + OFF_BSEG);

    // ---- prefetch B chunks 0 and 1 (each thread copies 128B per mat) ----
    {
        #pragma unroll
        for (int c = 0; c < 2; ++c) {
            const u32* s0 = g_Wb + (size_t)((c >> 2) * 8 + (c & 3)) * 8192 + tid * 32;
            u32 d0 = sb + OFF_B + (c & 1) * 65536 + tid * 128;
            #pragma unroll
            for (int j = 0; j < 8; ++j) {
                cpasync16(d0 + j * 16, s0 + j * 4);                   // hi
                cpasync16(d0 + 32768 + j * 16, s0 + 32768 + j * 4);   // lo
            }
            CPCOMMIT();
        }
    }

    // ---- bias + segment ids ----
    sb1[tid] = b1[tid];
    sb2[tid] = b2[tid];
    if (tid < BM) {
        int r = row0 + tid;
        int s = -1;
        if (r < N) {
            if (g_is64) s = (int)((const long long*)batch)[r];
            else        s = ((const int*)batch)[r];
        }
        bseg[tid] = s;
    }

    // ---- load x tile fp32 -> bf16 hi/lo into AHI/ALO ([64][264] padded) ----
    {
        const float4* xg = (const float4*)x;
        #pragma unroll
        for (int it = 0; it < 16; ++it) {
            int f = tid + it * 256;            // 4096 float4s
            int r = f >> 6, k4 = f & 63;
            float4 v = make_float4(0.f, 0.f, 0.f, 0.f);
            if (row0 + r < N) v = xg[(size_t)(row0 + r) * (H / 4) + k4];
            __nv_bfloat162 h01 = __floats2bfloat162_rn(v.x, v.y);
            __nv_bfloat162 h23 = __floats2bfloat162_rn(v.z, v.w);
            float2 f01 = __bfloat1622float2(h01);
            float2 f23 = __bfloat1622float2(h23);
            __nv_bfloat162 l01 = __floats2bfloat162_rn(v.x - f01.x, v.y - f01.y);
            __nv_bfloat162 l23 = __floats2bfloat162_rn(v.z - f23.x, v.w - f23.y);
            char* pa = smem + OFF_AHI + r * AS + k4 * 8;
            char* pl = smem + OFF_ALO + r * AS + k4 * 8;
            *(__nv_bfloat162*)pa = h01;  *(__nv_bfloat162*)(pa + 4) = h23;
            *(__nv_bfloat162*)pl = l01;  *(__nv_bfloat162*)(pl + 4) = l23;
        }
    }

    float acc[4][4][4];
    #pragma unroll
    for (int i = 0; i < 4; ++i)
        #pragma unroll
        for (int j = 0; j < 4; ++j)
            #pragma unroll
            for (int q = 0; q < 4; ++q) acc[i][j][q] = 0.f;

    // ---- 8 chunks: 0-3 GEMM1 (W1), 4-7 GEMM2 (W2); k-chunk = 64 ----
    #pragma unroll 1
    for (int c = 0; c < 8; ++c) {
        if (c < 7) asm volatile("cp.async.wait_group 1;");
        else       asm volatile("cp.async.wait_group 0;");
        __syncthreads();   // chunk c visible; x/h tile visible on first use

        // ---- GEMM boundary: h = relu(D1+b1) -> bf16 hi/lo back into A ----
        if (c == 4) {
            #pragma unroll
            for (int mt = 0; mt < 4; ++mt)
                #pragma unroll
                for (int nt = 0; nt < 4; ++nt) {
                    float* a4 = acc[mt][nt];
                    int r  = mt * 16 + (lane >> 2);
                    int cc = w * 32 + nt * 8 + (lane & 3) * 2;
                    float bx = sb1[cc], by = sb1[cc + 1];
                    float h0 = fmaxf(a4[0] + bx, 0.f), h1 = fmaxf(a4[1] + by, 0.f);
                    float h2 = fmaxf(a4[2] + bx, 0.f), h3 = fmaxf(a4[3] + by, 0.f);
                    __nv_bfloat162 hiA = __floats2bfloat162_rn(h0, h1);
                    __nv_bfloat162 hiB = __floats2bfloat162_rn(h2, h3);
                    float2 fA = __bfloat1622float2(hiA);
                    float2 fB = __bfloat1622float2(hiB);
                    __nv_bfloat162 loA = __floats2bfloat162_rn(h0 - fA.x, h1 - fA.y);
                    __nv_bfloat162 loB = __floats2bfloat162_rn(h2 - fB.x, h3 - fB.y);
                    *(__nv_bfloat162*)(smem + OFF_AHI + r * AS + cc * 2)       = hiA;
                    *(__nv_bfloat162*)(smem + OFF_AHI + (r + 8) * AS + cc * 2) = hiB;
                    *(__nv_bfloat162*)(smem + OFF_ALO + r * AS + cc * 2)       = loA;
                    *(__nv_bfloat162*)(smem + OFF_ALO + (r + 8) * AS + cc * 2) = loB;
                }
            __syncthreads();   // h visible to all warps before GEMM2
            #pragma unroll
            for (int i = 0; i < 4; ++i)
                #pragma unroll
                for (int j = 0; j < 4; ++j)
                    #pragma unroll
                    for (int q = 0; q < 4; ++q) acc[i][j][q] = 0.f;
        }

        // ---- compute chunk c: 4 k16-steps ----
        const u32 bbase = sb + OFF_B + (c & 1) * 65536;
        const int kg0 = (c & 3) * 64;
        #pragma unroll
        for (int ks = 0; ks < 4; ++ks) {
            const int k0 = kg0 + ks * 16;
            const u32 aoff = (lane & 15) * AS + (k0 + ((lane >> 4) << 3)) * 2;
            u32 ah[4][4], al[4][4];
            #pragma unroll
            for (int mt = 0; mt < 4; ++mt) {
                ldm4(ah[mt], sb + OFF_AHI + mt * 16 * AS + aoff);
                ldm4(al[mt], sb + OFF_ALO + mt * 16 * AS + aoff);
            }
            u32 bh[4][2], bl[4][2];
            #pragma unroll
            for (int nt = 0; nt < 4; ++nt) {
                u32 ba = bbase + (((ks * 32 + (w * 4 + nt)) * 32 + lane) << 3);
                lds64(bh[nt], ba);
                lds64(bl[nt], ba + 32768);
            }
            #pragma unroll
            for (int mt = 0; mt < 4; ++mt)
                #pragma unroll
                for (int nt = 0; nt < 4; ++nt) {
                    mma16816(acc[mt][nt], ah[mt], bh[nt]);   // hi*hi
                    mma16816(acc[mt][nt], al[mt], bh[nt]);   // lo*hi
                    mma16816(acc[mt][nt], ah[mt], bl[nt]);   // hi*lo
                }
        }
        __syncthreads();   // all reads of buf (c&1) done before refill

        // ---- prefetch chunk c+2 into buf (c&1) ----
        if (c + 2 < 8) {
            int n2 = c + 2;
            const u32* s0 = g_Wb + (size_t)((n2 >> 2) * 8 + (n2 & 3)) * 8192 + tid * 32;
            u32 d0 = sb + OFF_B + (n2 & 1) * 65536 + tid * 128;
            #pragma unroll
            for (int j = 0; j < 8; ++j) {
                cpasync16(d0 + j * 16, s0 + j * 4);
                cpasync16(d0 + 32768 + j * 16, s0 + 32768 + j * 4);
            }
            CPCOMMIT();
        }
    }

    // ---- final epilogue: g = h * sigmoid(D2 + b2) -> gtile ----
    float* gt = (float*)(smem + OFF_B);   // [64][257] fp32, B buffers dead
    #pragma unroll
    for (int mt = 0; mt < 4; ++mt)
        #pragma unroll
        for (int nt = 0; nt < 4; ++nt) {
            float* a4 = acc[mt][nt];
            int r  = mt * 16 + (lane >> 2);
            int cc = w * 32 + nt * 8 + (lane & 3) * 2;
            float bx = sb2[cc], by = sb2[cc + 1];
            float2 hA = __bfloat1622float2(*(__nv_bfloat162*)(smem + OFF_AHI + r * AS + cc * 2));
            float2 lA = __bfloat1622float2(*(__nv_bfloat162*)(smem + OFF_ALO + r * AS + cc * 2));
            float2 hB = __bfloat1622float2(*(__nv_bfloat162*)(smem + OFF_AHI + (r + 8) * AS + cc * 2));
            float2 lB = __bfloat1622float2(*(__nv_bfloat162*)(smem + OFF_ALO + (r + 8) * AS + cc * 2));
            float g0 = (hA.x + lA.x) / (1.f + __expf(-(a4[0] + bx)));
            float g1 = (hA.y + lA.y) / (1.f + __expf(-(a4[1] + by)));
            float g2 = (hB.x + lB.x) / (1.f + __expf(-(a4[2] + bx)));
            float g3 = (hB.y + lB.y) / (1.f + __expf(-(a4[3] + by)));
            gt[r * 257 + cc]           = g0;
            gt[r * 257 + cc + 1]       = g1;
            gt[(r + 8) * 257 + cc]     = g2;
            gt[(r + 8) * 257 + cc + 1] = g3;
        }
    __syncthreads();

    // ---- segment reduction: sorted batch -> runs; one thread per column ----
    {
        const int ccol = tid;              // 256 threads = 256 columns
        int cur = bseg[0];
        float rsum = 0.f, rmax = 0.f;
        #pragma unroll 1
        for (int r = 0; r < BM; ++r) {
            int s = bseg[r];
            float g = gt[r * 257 + ccol];
            if (s != cur) {
                if (cur >= 0) {
                    atomicAdd(&out[(size_t)cur * 2 * H + H + ccol], rsum);
                    atomicMax((unsigned int*)&out[(size_t)cur * 2 * H + ccol],
                              __float_as_uint(rmax));   // g >= 0 always
                }
                cur = s; rsum = 0.f; rmax = 0.f;
            }
            if (s >= 0) { rsum += g; rmax = fmaxf(rmax, g); }
        }
        if (cur >= 0) {
            atomicAdd(&out[(size_t)cur * 2 * H + H + ccol], rsum);
            atomicMax((unsigned int*)&out[(size_t)cur * 2 * H + ccol],
                      __float_as_uint(rmax));
        }
        if (tid == 0) {                    // counts: once per run per tile
            int cur2 = bseg[0]; int cnt = 0;
            for (int r = 0; r < BM; ++r) {
                int s = bseg[r];
                if (s != cur2) {
                    if (cur2 >= 0) atomicAdd(&g_counts[cur2], cnt);
                    cur2 = s; cnt = 0;
                }
                if (s >= 0) cnt++;
            }
            if (cur2 >= 0) atomicAdd(&g_counts[cur2], cnt);
        }
    }
}

// ---------------------------------------------------------------------------
// Kernel 4: mean = sum / count (empty segments stay 0)
// ---------------------------------------------------------------------------
__global__ void finalize_kernel(float* out) {
    int i = blockIdx.x * blockDim.x + threadIdx.x;  // NSEG * H
    if (i < NSEG * H) {
        int seg = i >> 8;
        int c   = i & (H - 1);
        int cnt = g_counts[seg];
        float denom = cnt > 0 ? (float)cnt : 1.f;
        out[(size_t)seg * 2 * H + H + c] *= (1.f / denom);
    }
}

extern "C" void kernel_launch(void* const* d_in, const int* in_sizes, int n_in,
                              void* d_out, int out_size) {
    const float* x     = (const float*)d_in[0];
    const void*  batch = d_in[1];
    const float* W1    = (const float*)d_in[2];
    const float* b1    = (const float*)d_in[3];
    const float* W2    = (const float*)d_in[4];
    const float* b2    = (const float*)d_in[5];
    float* out = (float*)d_out;

    int N = in_sizes[0] / H;

    cudaFuncSetAttribute(fused_kernel,
                         cudaFuncAttributeMaxDynamicSharedMemorySize, SMEM_TOTAL);

    zero_kernel<<<(out_size + 255) / 256, 256>>>(out, out_size, batch, N);
    wprep_kernel<<<512, 256>>>(W1, W2);

    int nblk = (N + BM - 1) / BM;
    fused_kernel<<<nblk, 256, SMEM_TOTAL>>>(x, batch, b1, b2, out, N);

    finalize_kernel<<<(NSEG * H + 255) / 256, 256>>>(out);
}

// round 6
// speedup vs baseline: 3.2372x; 2.3162x over previous
#include <cuda_runtime.h>
#include <cuda_bf16.h>
#include <cstdint>
#include <math.h>

#define H 256
#define BM 64
#define NSEG 512
#define AS 528           // A row stride in bytes (264 bf16, padded)

typedef unsigned long long u64;
typedef unsigned int       u32;

// -------- device scratch (no allocations allowed) --------
__device__ int g_counts[NSEG];
__device__ int g_is64;
// W packed in per-lane b-fragment layout:
// [gemm(2)][mat hi/lo(2)][kchunk(4)] blocks of 8192 u32 = [ks(4)][nt(32)][lane(32)][reg(2)]
__device__ __align__(16) u32 g_Wb[131072];

// -------- SMEM layout (bytes) --------
#define OFF_AHI   0                    // [64][264] bf16 = 33792
#define OFF_ALO   33792                // 33792
#define OFF_BSEG  67584                // 64 ints = 256
#define OFF_BIAS  67840                // b1[256], b2[256] fp32 = 2048
#define SMEM_TOTAL 69888
// g tile (final): fp32 [64][264] overlays AHI/ALO (written after an extra sync)

// -------- PTX helpers (legal on plain sm_103 target) --------
__device__ __forceinline__ void ldm4(u32* r, u32 addr) {
    asm volatile("ldmatrix.sync.aligned.m8n8.x4.shared.b16 {%0,%1,%2,%3},[%4];"
        : "=r"(r[0]), "=r"(r[1]), "=r"(r[2]), "=r"(r[3]) : "r"(addr));
}
__device__ __forceinline__ void mma16816(float* d, const u32* a, const u32* b) {
    asm volatile(
        "mma.sync.aligned.m16n8k16.row.col.f32.bf16.bf16.f32 "
        "{%0,%1,%2,%3},{%4,%5,%6,%7},{%8,%9},{%0,%1,%2,%3};"
        : "+f"(d[0]), "+f"(d[1]), "+f"(d[2]), "+f"(d[3])
        : "r"(a[0]), "r"(a[1]), "r"(a[2]), "r"(a[3]), "r"(b[0]), "r"(b[1]));
}

// ---------------------------------------------------------------------------
// Kernel 1: zero output + counts, detect batch dtype (int64 vs int32).
// ---------------------------------------------------------------------------
__global__ void zero_kernel(float* out, int out_size, const void* batch, int N) {
    int i = blockIdx.x * blockDim.x + threadIdx.x;
    if (i < out_size) out[i] = 0.0f;
    if (i < NSEG) g_counts[i] = 0;
    if (i == 0) {
        const int* bw = (const int*)batch;
        int o = ((N - 1) & 1) ? (N - 1) : (N - 2);
        int orv = 0;
        if (o >= 4) orv = bw[o] | bw[o - 2] | bw[o - 4];
        else if (o >= 0) orv = bw[o];
        g_is64 = (orv == 0) ? 1 : 0;
    }
}

// ---------------------------------------------------------------------------
// Kernel 2: split W1/W2 fp32 -> bf16 hi/lo, packed in mma b-fragment layout.
// (identical to R5 — verified correct)
// ---------------------------------------------------------------------------
__global__ void wprep_kernel(const float* __restrict__ W1,
                             const float* __restrict__ W2) {
    int id = blockIdx.x * 256 + threadIdx.x;     // 131072 total
    int gemm = id >> 16, rem = id & 65535;
    int n = rem >> 8, k = rem & 255;
    float w = (gemm ? W2 : W1)[n * H + k];
    __nv_bfloat16 hi = __float2bfloat16(w);
    __nv_bfloat16 lo = __float2bfloat16(w - __bfloat162float(hi));
    int chunk = k >> 6, ks = (k >> 4) & 3, kk = k & 15;
    int nt = n >> 3, nn = n & 7;
    int lane = nn * 4 + ((kk & 7) >> 1);
    int reg  = kk >> 3;
    int half = kk & 1;
    u32 base = (u32)(((gemm * 2 + 0) * 4 + chunk) * 8192
                     + ((ks * 32 + nt) * 32 + lane) * 2 + reg);
    __nv_bfloat16* wb = (__nv_bfloat16*)g_Wb;
    wb[(size_t)base * 2 + half] = hi;                       // mat 0 (hi)
    wb[((size_t)base + 32768) * 2 + half] = lo;             // mat 1 (lo)
}

// ---------------------------------------------------------------------------
// Kernel 3: fused  relu(xW1^T+b1) -> sigmoid(hW2^T+b2) gate -> segment reduce.
// bf16 HMMA, 3-term hi/lo compensation. B-fragments loaded straight from
// global (prepacked layout, coalesced LDG.64) -> no B smem -> 2 CTAs/SM.
// ---------------------------------------------------------------------------
extern "C" __global__ void __launch_bounds__(256, 2)
fused_kernel(const float* __restrict__ x, const void* __restrict__ batch,
             const float* __restrict__ b1, const float* __restrict__ b2,
             float* __restrict__ out, int N)
{
    extern __shared__ char smem[];
    const u32 sb = (u32)__cvta_generic_to_shared(smem);
    const int tid  = threadIdx.x;
    const int w    = tid >> 5;          // warp 0..7: output cols w*32..w*32+31
    const int lane = tid & 31;
    const int row0 = blockIdx.x * BM;
    float* sb1 = (float*)(smem + OFF_BIAS);
    float* sb2 = sb1 + H;
    int* bseg = (int*)(smem + OFF_BSEG);

    // ---- bias + segment ids ----
    sb1[tid] = b1[tid];
    sb2[tid] = b2[tid];
    if (tid < BM) {
        int r = row0 + tid;
        int s = -1;
        if (r < N) {
            if (g_is64) s = (int)((const long long*)batch)[r];
            else        s = ((const int*)batch)[r];
        }
        bseg[tid] = s;
    }

    // ---- load x tile fp32 -> bf16 hi/lo into AHI/ALO ([64][264] padded) ----
    {
        const float4* xg = (const float4*)x;
        #pragma unroll
        for (int it = 0; it < 16; ++it) {
            int f = tid + it * 256;            // 4096 float4s
            int r = f >> 6, k4 = f & 63;
            float4 v = make_float4(0.f, 0.f, 0.f, 0.f);
            if (row0 + r < N) v = xg[(size_t)(row0 + r) * (H / 4) + k4];
            __nv_bfloat162 h01 = __floats2bfloat162_rn(v.x, v.y);
            __nv_bfloat162 h23 = __floats2bfloat162_rn(v.z, v.w);
            float2 f01 = __bfloat1622float2(h01);
            float2 f23 = __bfloat1622float2(h23);
            __nv_bfloat162 l01 = __floats2bfloat162_rn(v.x - f01.x, v.y - f01.y);
            __nv_bfloat162 l23 = __floats2bfloat162_rn(v.z - f23.x, v.w - f23.y);
            char* pa = smem + OFF_AHI + r * AS + k4 * 8;
            char* pl = smem + OFF_ALO + r * AS + k4 * 8;
            *(__nv_bfloat162*)pa = h01;  *(__nv_bfloat162*)(pa + 4) = h23;
            *(__nv_bfloat162*)pl = l01;  *(__nv_bfloat162*)(pl + 4) = l23;
        }
    }
    __syncthreads();   // x tile visible to all warps

    float acc[4][4][4];
    #pragma unroll
    for (int i = 0; i < 4; ++i)
        #pragma unroll
        for (int j = 0; j < 4; ++j)
            #pragma unroll
            for (int q = 0; q < 4; ++q) acc[i][j][q] = 0.f;

    // ---- 2 GEMMs, K=256 = 16 k16-steps each; B double-buffered in regs ----
    #pragma unroll 1
    for (int g = 0; g < 2; ++g) {
        const u32* bh_base = g_Wb + g * 65536;        // hi blocks
        const u32* bl_base = bh_base + 32768;         // lo blocks
        const u32 lwo = (u32)((w * 4) * 32 + lane) * 2;   // per-warp lane offset (u32)

        uint2 bh[2][4], bl[2][4];
        // preload ks = 0
        #pragma unroll
        for (int nt = 0; nt < 4; ++nt) {
            u32 o = lwo + nt * 64;
            bh[0][nt] = *(const uint2*)(bh_base + o);
            bl[0][nt] = *(const uint2*)(bl_base + o);
        }

        #pragma unroll 2
        for (int ks = 0; ks < 16; ++ks) {
            const int cur = ks & 1, nxt = cur ^ 1;
            // prefetch next k16-step's B fragments (hidden under MMAs)
            if (ks < 15) {
                int k1 = ks + 1;
                u32 ob = (u32)(k1 >> 2) * 8192 + (u32)((k1 & 3) * 32) * 64 + lwo;
                #pragma unroll
                for (int nt = 0; nt < 4; ++nt) {
                    bh[nxt][nt] = *(const uint2*)(bh_base + ob + nt * 64);
                    bl[nxt][nt] = *(const uint2*)(bl_base + ob + nt * 64);
                }
            }
            // A fragments + MMAs
            const u32 aoff = (lane & 15) * AS + (ks * 16 + ((lane >> 4) << 3)) * 2;
            #pragma unroll
            for (int mt = 0; mt < 4; ++mt) {
                u32 ah[4], al[4];
                ldm4(ah, sb + OFF_AHI + mt * 16 * AS + aoff);
                ldm4(al, sb + OFF_ALO + mt * 16 * AS + aoff);
                #pragma unroll
                for (int nt = 0; nt < 4; ++nt) {
                    mma16816(acc[mt][nt], ah, (const u32*)&bh[cur][nt]);  // hi*hi
                    mma16816(acc[mt][nt], al, (const u32*)&bh[cur][nt]);  // lo*hi
                    mma16816(acc[mt][nt], ah, (const u32*)&bl[cur][nt]);  // hi*lo
                }
            }
        }

        // ---- GEMM boundary: h = relu(D1+b1) -> bf16 hi/lo back into A ----
        if (g == 0) {
            __syncthreads();   // all warps done READING x before overwrite
            #pragma unroll
            for (int mt = 0; mt < 4; ++mt)
                #pragma unroll
                for (int nt = 0; nt < 4; ++nt) {
                    float* a4 = acc[mt][nt];
                    int r  = mt * 16 + (lane >> 2);
                    int cc = w * 32 + nt * 8 + (lane & 3) * 2;
                    float bx = sb1[cc], by = sb1[cc + 1];
                    float h0 = fmaxf(a4[0] + bx, 0.f), h1 = fmaxf(a4[1] + by, 0.f);
                    float h2 = fmaxf(a4[2] + bx, 0.f), h3 = fmaxf(a4[3] + by, 0.f);
                    __nv_bfloat162 hiA = __floats2bfloat162_rn(h0, h1);
                    __nv_bfloat162 hiB = __floats2bfloat162_rn(h2, h3);
                    float2 fA = __bfloat1622float2(hiA);
                    float2 fB = __bfloat1622float2(hiB);
                    __nv_bfloat162 loA = __floats2bfloat162_rn(h0 - fA.x, h1 - fA.y);
                    __nv_bfloat162 loB = __floats2bfloat162_rn(h2 - fB.x, h3 - fB.y);
                    *(__nv_bfloat162*)(smem + OFF_AHI + r * AS + cc * 2)       = hiA;
                    *(__nv_bfloat162*)(smem + OFF_AHI + (r + 8) * AS + cc * 2) = hiB;
                    *(__nv_bfloat162*)(smem + OFF_ALO + r * AS + cc * 2)       = loA;
                    *(__nv_bfloat162*)(smem + OFF_ALO + (r + 8) * AS + cc * 2) = loB;
                }
            __syncthreads();   // h visible to all warps before GEMM2
            #pragma unroll
            for (int i = 0; i < 4; ++i)
                #pragma unroll
                for (int j = 0; j < 4; ++j)
                    #pragma unroll
                    for (int q = 0; q < 4; ++q) acc[i][j][q] = 0.f;
        }
    }

    // ---- final epilogue: g = h * sigmoid(D2+b2); g overlays A region ----
    float* gt = (float*)smem;   // [64][264] fp32 over AHI+ALO
    {
        float gv[4][4][4];
        #pragma unroll
        for (int mt = 0; mt < 4; ++mt)
            #pragma unroll
            for (int nt = 0; nt < 4; ++nt) {
                float* a4 = acc[mt][nt];
                int r  = mt * 16 + (lane >> 2);
                int cc = w * 32 + nt * 8 + (lane & 3) * 2;
                float bx = sb2[cc], by = sb2[cc + 1];
                float2 hA = __bfloat1622float2(*(__nv_bfloat162*)(smem + OFF_AHI + r * AS + cc * 2));
                float2 lA = __bfloat1622float2(*(__nv_bfloat162*)(smem + OFF_ALO + r * AS + cc * 2));
                float2 hB = __bfloat1622float2(*(__nv_bfloat162*)(smem + OFF_AHI + (r + 8) * AS + cc * 2));
                float2 lB = __bfloat1622float2(*(__nv_bfloat162*)(smem + OFF_ALO + (r + 8) * AS + cc * 2));
                gv[mt][nt][0] = (hA.x + lA.x) / (1.f + __expf(-(a4[0] + bx)));
                gv[mt][nt][1] = (hA.y + lA.y) / (1.f + __expf(-(a4[1] + by)));
                gv[mt][nt][2] = (hB.x + lB.x) / (1.f + __expf(-(a4[2] + bx)));
                gv[mt][nt][3] = (hB.y + lB.y) / (1.f + __expf(-(a4[3] + by)));
            }
        __syncthreads();   // everyone done reading h before overwrite
        #pragma unroll
        for (int mt = 0; mt < 4; ++mt)
            #pragma unroll
            for (int nt = 0; nt < 4; ++nt) {
                int r  = mt * 16 + (lane >> 2);
                int cc = w * 32 + nt * 8 + (lane & 3) * 2;
                *(float2*)&gt[r * 264 + cc]       = make_float2(gv[mt][nt][0], gv[mt][nt][1]);
                *(float2*)&gt[(r + 8) * 264 + cc] = make_float2(gv[mt][nt][2], gv[mt][nt][3]);
            }
    }
    __syncthreads();

    // ---- segment reduction: sorted batch -> runs; one thread per column ----
    {
        const int ccol = tid;              // 256 threads = 256 columns
        int cur = bseg[0];
        float rsum = 0.f, rmax = 0.f;
        #pragma unroll 1
        for (int r = 0; r < BM; ++r) {
            int s = bseg[r];
            float g = gt[r * 264 + ccol];
            if (s != cur) {
                if (cur >= 0) {
                    atomicAdd(&out[(size_t)cur * 2 * H + H + ccol], rsum);
                    atomicMax((unsigned int*)&out[(size_t)cur * 2 * H + ccol],
                              __float_as_uint(rmax));   // g >= 0 always
                }
                cur = s; rsum = 0.f; rmax = 0.f;
            }
            if (s >= 0) { rsum += g; rmax = fmaxf(rmax, g); }
        }
        if (cur >= 0) {
            atomicAdd(&out[(size_t)cur * 2 * H + H + ccol], rsum);
            atomicMax((unsigned int*)&out[(size_t)cur * 2 * H + ccol],
                      __float_as_uint(rmax));
        }
        if (tid == 0) {                    // counts: once per run per tile
            int cur2 = bseg[0]; int cnt = 0;
            for (int r = 0; r < BM; ++r) {
                int s = bseg[r];
                if (s != cur2) {
                    if (cur2 >= 0) atomicAdd(&g_counts[cur2], cnt);
                    cur2 = s; cnt = 0;
                }
                if (s >= 0) cnt++;
            }
            if (cur2 >= 0) atomicAdd(&g_counts[cur2], cnt);
        }
    }
}

// ---------------------------------------------------------------------------
// Kernel 4: mean = sum / count (empty segments stay 0)
// ---------------------------------------------------------------------------
__global__ void finalize_kernel(float* out) {
    int i = blockIdx.x * blockDim.x + threadIdx.x;  // NSEG * H
    if (i < NSEG * H) {
        int seg = i >> 8;
        int c   = i & (H - 1);
        int cnt = g_counts[seg];
        float denom = cnt > 0 ? (float)cnt : 1.f;
        out[(size_t)seg * 2 * H + H + c] *= (1.f / denom);
    }
}

extern "C" void kernel_launch(void* const* d_in, const int* in_sizes, int n_in,
                              void* d_out, int out_size) {
    const float* x     = (const float*)d_in[0];
    const void*  batch = d_in[1];
    const float* W1    = (const float*)d_in[2];
    const float* b1    = (const float*)d_in[3];
    const float* W2    = (const float*)d_in[4];
    const float* b2    = (const float*)d_in[5];
    float* out = (float*)d_out;

    int N = in_sizes[0] / H;

    cudaFuncSetAttribute(fused_kernel,
                         cudaFuncAttributeMaxDynamicSharedMemorySize, SMEM_TOTAL);

    zero_kernel<<<(out_size + 255) / 256, 256>>>(out, out_size, batch, N);
    wprep_kernel<<<512, 256>>>(W1, W2);

    int nblk = (N + BM - 1) / BM;
    fused_kernel<<<nblk, 256, SMEM_TOTAL>>>(x, batch, b1, b2, out, N);

    finalize_kernel<<<(NSEG * H + 255) / 256, 256>>>(out);
}